// round 6
// baseline (speedup 1.0000x reference)
#include <cuda_runtime.h>
#include <cstdint>
#include <cstddef>

// Problem constants
#define B_  256
#define T_  1024
#define I_  8
#define H_  256
#define L_  32          // steps per chunk
#define C_  32          // number of chunks (C_*L_ == T_)
#define BH  (B_*H_)
#define R_  64          // batch rows per scan CTA
#define NRG (B_/R_)     // 4 row groups -> 128 scan CTAs
#define NP  (B_/2)      // 128 row-pairs

// ---------------- device scratch (no allocations allowed) ----------------
// Row-paired layouts: element [pair][h] = {value(row 2*pair), value(row 2*pair+1)}
__device__ float2 g_xw2[(size_t)T_ * NP * H_];     // input projections, paired
__device__ float  g_At[H_ * H_];                   // A = Wh^T  (h_new = h @ A)
__device__ float  g_T1[H_ * H_];
__device__ float  g_T2[H_ * H_];
__device__ float  g_P32[H_ * H_];                  // A^32
__device__ float2 g_Zend2[(size_t)C_ * NP * H_];   // chunk-final partials, paired
__device__ float2 g_Hstart2[(size_t)C_ * NP * H_]; // chunk start states, paired

// ---------------- packed f32x2 helpers ----------------
__device__ __forceinline__ unsigned long long pack2(float v) {
    unsigned long long r;
    asm("mov.b64 %0, {%1, %1};" : "=l"(r) : "f"(v));
    return r;
}
__device__ __forceinline__ unsigned long long packab(float a, float b) {
    unsigned long long r;
    asm("mov.b64 %0, {%1, %2};" : "=l"(r) : "f"(a), "f"(b));
    return r;
}
__device__ __forceinline__ void fma2(unsigned long long& d,
                                     unsigned long long a,
                                     unsigned long long b) {
    asm("fma.rn.f32x2 %0, %1, %2, %0;" : "+l"(d) : "l"(a), "l"(b));
}
__device__ __forceinline__ float lof(unsigned long long v) {
    return __uint_as_float((unsigned)v);
}
__device__ __forceinline__ float hif(unsigned long long v) {
    return __uint_as_float((unsigned)(v >> 32));
}

// ---------------- out[0] = broadcast h0 ----------------
__global__ void k_out0(float* __restrict__ out, const float* __restrict__ h0) {
    int idx = blockIdx.x * 256 + threadIdx.x;           // 65536 total
    out[idx] = h0[idx & (H_ - 1)];
}

// ---------------- xw[t] = x[:,t,:] @ Wx^T  (paired output) ----------------
__global__ void k_xw(const float* __restrict__ x, const float* __restrict__ Wx) {
    const int t   = blockIdx.x;       // 0..T-1
    const int tau = threadIdx.x;      // = output h index
    float wx[I_];
#pragma unroll
    for (int i = 0; i < I_; i++) wx[i] = Wx[tau * I_ + i];

    __shared__ float xs[32][I_];
    const int br = tau >> 3;          // 0..31
    const int ii = tau & 7;

    for (int b0 = 0; b0 < B_; b0 += 32) {
        xs[br][ii] = x[((size_t)(b0 + br) * T_ + t) * I_ + ii];
        __syncthreads();
#pragma unroll 4
        for (int pr = 0; pr < 16; pr++) {
            float s0 = 0.f, s1 = 0.f;
#pragma unroll
            for (int i = 0; i < I_; i++) {
                s0 += xs[2 * pr + 0][i] * wx[i];
                s1 += xs[2 * pr + 1][i] * wx[i];
            }
            g_xw2[((size_t)t * NP + (b0 >> 1) + pr) * H_ + tau] = make_float2(s0, s1);
        }
        __syncthreads();
    }
}

// ---------------- g_At = Wh^T ----------------
__global__ void k_transpose(const float* __restrict__ Wh) {
    int idx = blockIdx.x * 256 + threadIdx.x;   // 65536
    int h  = idx >> 8;
    int h2 = idx & 255;
    g_At[idx] = Wh[h2 * H_ + h];                // A[h][h'] = Wh[h'][h]
}

// ---------------- squaring chain for A^32 ----------------
__global__ void k_square(int step) {
    const float* src;
    float* dst;
    switch (step) {
        case 0: src = g_At; dst = g_T1;  break;   // A^2
        case 1: src = g_T1; dst = g_T2;  break;   // A^4
        case 2: src = g_T2; dst = g_T1;  break;   // A^8
        case 3: src = g_T1; dst = g_T2;  break;   // A^16
        default:src = g_T2; dst = g_P32; break;   // A^32
    }
    __shared__ float as[32][33], bs[32][33];
    const int tx = threadIdx.x & 31;
    const int ty = threadIdx.x >> 5;            // 0..7
    const int row0 = blockIdx.y * 32, col0 = blockIdx.x * 32;
    float acc[4] = {0.f, 0.f, 0.f, 0.f};
    for (int k0 = 0; k0 < H_; k0 += 32) {
#pragma unroll
        for (int e = 0; e < 4; e++) {
            int r = ty + e * 8;
            as[r][tx] = src[(size_t)(row0 + r) * H_ + k0 + tx];
            bs[r][tx] = src[(size_t)(k0 + r) * H_ + col0 + tx];
        }
        __syncthreads();
#pragma unroll
        for (int kk = 0; kk < 32; kk++) {
            float bv = bs[kk][tx];
#pragma unroll
            for (int e = 0; e < 4; e++) acc[e] += as[ty + e * 8][kk] * bv;
        }
        __syncthreads();
    }
#pragma unroll
    for (int e = 0; e < 4; e++)
        dst[(size_t)(row0 + ty + e * 8) * H_ + col0 + tx] = acc[e];
}

// ---------------- chunked scan (row-paired f32x2) ----------------
// R_=64 rows/CTA (32 pairs), 128 CTAs, 1 CTA/SM, smem 128 KB.
// Warp tile: 16 rows (8 pairs) x 128 cols; lane owns 4 cols of one col-half.
// z lives in smem as float2 {even,odd} per (pair,h): the f32x2 b-operand comes
// straight from LDS.128 (no pack MOVs). A row is 1 coalesced LDG.128 per warp
// per h (4 wavefronts), duplicated into both lanes via 8 MOVs.
// PASS 0: zero-init scan, stores only Zend. PASS 1: from Hstart, writes out.
template <int PASS>
__global__ void __launch_bounds__(256, 1) k_scan(float* __restrict__ out) {
    extern __shared__ float2 smz[];
    float2* zb[2] = { smz, smz + 32 * H_ };

    const int c   = blockIdx.x & (C_ - 1);    // chunk
    const int rg  = blockIdx.x >> 5;          // row group 0..3
    const int pr0 = rg * 32;                  // CTA base pair (global)
    const int tau = threadIdx.x;
    const int w   = tau >> 5;                 // warp 0..7
    const int l   = tau & 31;
    const int pb  = (w >> 1) * 8;             // local pair base (0,8,16,24)
    const int c0  = (w & 1) * 128 + l * 4;    // 4 cols per lane

    // init z buffer: PASS0 -> xw of first step; PASS1 -> Hstart (linear copy)
    {
        const float2* src = (PASS == 0)
            ? (g_xw2 + ((size_t)(c * L_) * NP + pr0) * H_)
            : (g_Hstart2 + ((size_t)c * NP + pr0) * H_);
        const ulonglong2* s = (const ulonglong2*)src;
        ulonglong2* d = (ulonglong2*)zb[0];
#pragma unroll
        for (int k = 0; k < 16; k++) d[tau + k * 256] = s[tau + k * 256];
    }
    __syncthreads();

    int p = 0;
    const int jstart = (PASS == 0) ? 2 : 1;

    for (int j = jstart; j <= L_; ++j) {
        const int t = c * L_ + j;             // global time step (1..T)
        unsigned long long acc[8][4];         // 8 pairs x 4 cols, {even,odd}
#pragma unroll
        for (int i = 0; i < 8; i++) {
            const float2* xr = g_xw2 + ((size_t)(t - 1) * NP + pr0 + pb + i) * H_ + c0;
            ulonglong2 x0 = *(const ulonglong2*)xr;
            ulonglong2 x1 = *(const ulonglong2*)(xr + 2);
            acc[i][0] = x0.x; acc[i][1] = x0.y;
            acc[i][2] = x1.x; acc[i][3] = x1.y;
        }
        const float2* zr = zb[p] + pb * H_;
#pragma unroll 2
        for (int hg = 0; hg < H_ / 2; ++hg) {
            ulonglong2 q[8];                   // {pair@2hg, pair@2hg+1}
#pragma unroll
            for (int i = 0; i < 8; i++)
                q[i] = *(const ulonglong2*)(zr + i * H_ + 2 * hg);
#pragma unroll
            for (int hh = 0; hh < 2; hh++) {
                const float4 a4 = *(const float4*)(g_At + (2 * hg + hh) * H_ + c0);
                unsigned long long d0 = pack2(a4.x), d1 = pack2(a4.y),
                                   d2 = pack2(a4.z), d3 = pack2(a4.w);
#pragma unroll
                for (int i = 0; i < 8; i++) {
                    unsigned long long zz = hh ? q[i].y : q[i].x;
                    fma2(acc[i][0], zz, d0);
                    fma2(acc[i][1], zz, d1);
                    fma2(acc[i][2], zz, d2);
                    fma2(acc[i][3], zz, d3);
                }
            }
        }
#pragma unroll
        for (int i = 0; i < 8; i++) {
            float2* zw = zb[p ^ 1] + (pb + i) * H_ + c0;
            *(ulonglong2*)zw       = make_ulonglong2(acc[i][0], acc[i][1]);
            *(ulonglong2*)(zw + 2) = make_ulonglong2(acc[i][2], acc[i][3]);
            if (PASS == 1) {
                const int row = 2 * (pr0 + pb + i);
                float* o = out + (size_t)t * BH + (size_t)row * H_ + c0;
                *(float4*)o = make_float4(lof(acc[i][0]), lof(acc[i][1]),
                                          lof(acc[i][2]), lof(acc[i][3]));
                *(float4*)(o + H_) = make_float4(hif(acc[i][0]), hif(acc[i][1]),
                                                 hif(acc[i][2]), hif(acc[i][3]));
            }
        }
        __syncthreads();
        p ^= 1;
    }

    if (PASS == 0) {
        const ulonglong2* s = (const ulonglong2*)zb[p];
        ulonglong2* d = (ulonglong2*)(g_Zend2 + ((size_t)c * NP + pr0) * H_);
#pragma unroll
        for (int k = 0; k < 16; k++) d[tau + k * 256] = s[tau + k * 256];
    }
}

// ---------------- carry: Hstart[c+1] = Hstart[c] @ A^32 + Zend[c] ----------------
__global__ void __launch_bounds__(256, 1) k_carry(const float* __restrict__ h0) {
    __shared__ float hb[2][4 * H_];
    const int r0   = blockIdx.x * 4;          // 64 blocks x 4 rows
    const int tau  = threadIdx.x;
    const int rowg = tau >> 6;                // 0..3
    const int lg   = tau & 63;
    const int c0   = lg * 4;                  // 4 output cols per thread
    const int row  = r0 + rowg;
    const int pi   = row >> 1;                // pair index
    const int par  = row & 1;

    // Hstart[0] = broadcast h0 (paired layout)
#pragma unroll
    for (int e = 0; e < 4; e++) {
        float v = h0[tau];
        hb[0][e * H_ + tau] = v;
        int rr = r0 + e;
        ((float*)g_Hstart2)[(((size_t)(rr >> 1)) * H_ + tau) * 2 + (rr & 1)] = v;
    }
    __syncthreads();

    int p = 0;
    for (int cc = 0; cc < C_ - 1; cc++) {
        const float* zsf = (const float*)
            (g_Zend2 + ((size_t)cc * NP + pi) * H_ + c0);
        unsigned long long acc[2];
        acc[0] = packab(zsf[0 + par], zsf[2 + par]);
        acc[1] = packab(zsf[4 + par], zsf[6 + par]);
        const float* zrow = hb[p] + rowg * H_;
#pragma unroll 4
        for (int h = 0; h < H_; h++) {
            ulonglong2 aa = *(const ulonglong2*)(g_P32 + h * H_ + c0);
            unsigned long long zz = pack2(zrow[h]);
            fma2(acc[0], zz, aa.x);
            fma2(acc[1], zz, aa.y);
        }
        unsigned long long* wsm = (unsigned long long*)(hb[p ^ 1] + rowg * H_ + c0);
        wsm[0] = acc[0]; wsm[1] = acc[1];
        float* g = (float*)g_Hstart2
                 + (((size_t)(cc + 1) * NP + pi) * H_ + c0) * 2 + par;
        g[0] = lof(acc[0]); g[2] = hif(acc[0]);
        g[4] = lof(acc[1]); g[6] = hif(acc[1]);
        __syncthreads();
        p ^= 1;
    }
}

// ---------------- launch ----------------
extern "C" void kernel_launch(void* const* d_in, const int* in_sizes, int n_in,
                              void* d_out, int out_size) {
    (void)in_sizes; (void)n_in; (void)out_size;
    const float* x  = (const float*)d_in[0];
    const float* Wh = (const float*)d_in[1];
    const float* Wx = (const float*)d_in[2];
    const float* h0 = (const float*)d_in[3];
    float* out = (float*)d_out;

    const int smem = 2 * 32 * H_ * (int)sizeof(float2);   // 131072 bytes
    cudaFuncSetAttribute(k_scan<0>, cudaFuncAttributeMaxDynamicSharedMemorySize, smem);
    cudaFuncSetAttribute(k_scan<1>, cudaFuncAttributeMaxDynamicSharedMemorySize, smem);

    // ncu captures MY 0-based launch index 3 -> keep k_scan<0> there.
    k_xw<<<T_, 256>>>(x, Wx);                          // 0
    k_transpose<<<256, 256>>>(Wh);                     // 1
    k_out0<<<256, 256>>>(out, h0);                     // 2
    k_scan<0><<<C_ * NRG, 256, smem>>>(out);           // 3  partials -> Zend (PROFILED)
    dim3 g8(8, 8);
    k_square<<<g8, 256>>>(0);                          // 4  A^2
    k_square<<<g8, 256>>>(1);                          // 5  A^4
    k_square<<<g8, 256>>>(2);                          // 6  A^8
    k_square<<<g8, 256>>>(3);                          // 7  A^16
    k_square<<<g8, 256>>>(4);                          // 8  A^32
    k_carry<<<B_ / 4, 256>>>(h0);                      // 9  chunk start states
    k_scan<1><<<C_ * NRG, 256, smem>>>(out);           // 10 final scan -> out
}

// round 7
// speedup vs baseline: 1.1253x; 1.1253x over previous
#include <cuda_runtime.h>
#include <cstdint>
#include <cstddef>

// Problem constants
#define B_  256
#define T_  1024
#define I_  8
#define H_  256
#define L_  32          // steps per chunk
#define C_  32          // number of chunks (C_*L_ == T_)
#define BH  (B_*H_)
#define R_  64          // batch rows per scan CTA
#define NRG (B_/R_)     // 4 row groups -> 128 scan CTAs
#define TROWS 32        // A-tile rows staged per cp.async stage

// ---------------- device scratch (no allocations allowed) ----------------
__device__ float g_xw[(size_t)T_ * BH];      // input projections xw[t][b][h]
__device__ float g_At[H_ * H_];              // A = Wh^T  (h_new = h @ A)
__device__ float g_T1[H_ * H_];
__device__ float g_T2[H_ * H_];
__device__ float g_P32[H_ * H_];             // A^32
__device__ float g_Zend[(size_t)C_ * BH];    // chunk-final partials (zero-init scans)
__device__ float g_Hstart[(size_t)C_ * BH];  // true chunk start states

// ---------------- packed f32x2 helpers ----------------
__device__ __forceinline__ unsigned long long pack2(float v) {
    unsigned long long r;
    asm("mov.b64 %0, {%1, %1};" : "=l"(r) : "f"(v));
    return r;
}
__device__ __forceinline__ void fma2(unsigned long long& d,
                                     unsigned long long a,
                                     unsigned long long b) {
    asm("fma.rn.f32x2 %0, %1, %2, %0;" : "+l"(d) : "l"(a), "l"(b));
}
__device__ __forceinline__ float lof(unsigned long long v) {
    return __uint_as_float((unsigned)v);
}
__device__ __forceinline__ float hif(unsigned long long v) {
    return __uint_as_float((unsigned)(v >> 32));
}

// ---------------- cp.async helpers ----------------
__device__ __forceinline__ void cp16(uint32_t saddr, const void* g) {
    asm volatile("cp.async.cg.shared.global [%0], [%1], 16;"
                 :: "r"(saddr), "l"(g));
}
__device__ __forceinline__ void cp_commit() {
    asm volatile("cp.async.commit_group;");
}
__device__ __forceinline__ void cp_wait1() {
    asm volatile("cp.async.wait_group 1;");
}
__device__ __forceinline__ void cp_wait0() {
    asm volatile("cp.async.wait_group 0;");
}

// ---------------- out[0] = broadcast h0 ----------------
__global__ void k_out0(float* __restrict__ out, const float* __restrict__ h0) {
    int idx = blockIdx.x * 256 + threadIdx.x;           // 65536 total
    out[idx] = h0[idx & (H_ - 1)];
}

// ---------------- xw[t] = x[:,t,:] @ Wx^T ----------------
__global__ void k_xw(const float* __restrict__ x, const float* __restrict__ Wx) {
    const int t   = blockIdx.x;       // 0..T-1
    const int tau = threadIdx.x;      // = output h index
    float wx[I_];
#pragma unroll
    for (int i = 0; i < I_; i++) wx[i] = Wx[tau * I_ + i];

    __shared__ float xs[32][I_];
    const int br = tau >> 3;          // 0..31
    const int ii = tau & 7;

    for (int b0 = 0; b0 < B_; b0 += 32) {
        xs[br][ii] = x[((size_t)(b0 + br) * T_ + t) * I_ + ii];
        __syncthreads();
#pragma unroll 4
        for (int bb = 0; bb < 32; bb++) {
            float s = 0.f;
#pragma unroll
            for (int i = 0; i < I_; i++) s += xs[bb][i] * wx[i];
            __stcs(&g_xw[((size_t)t * B_ + (b0 + bb)) * H_ + tau], s);
        }
        __syncthreads();
    }
}

// ---------------- g_At = Wh^T ----------------
__global__ void k_transpose(const float* __restrict__ Wh) {
    int idx = blockIdx.x * 256 + threadIdx.x;   // 65536
    int h  = idx >> 8;
    int h2 = idx & 255;
    g_At[idx] = Wh[h2 * H_ + h];                // A[h][h'] = Wh[h'][h]
}

// ---------------- squaring chain for A^32 ----------------
__global__ void k_square(int step) {
    const float* src;
    float* dst;
    switch (step) {
        case 0: src = g_At; dst = g_T1;  break;   // A^2
        case 1: src = g_T1; dst = g_T2;  break;   // A^4
        case 2: src = g_T2; dst = g_T1;  break;   // A^8
        case 3: src = g_T1; dst = g_T2;  break;   // A^16
        default:src = g_T2; dst = g_P32; break;   // A^32
    }
    __shared__ float as[32][33], bs[32][33];
    const int tx = threadIdx.x & 31;
    const int ty = threadIdx.x >> 5;            // 0..7
    const int row0 = blockIdx.y * 32, col0 = blockIdx.x * 32;
    float acc[4] = {0.f, 0.f, 0.f, 0.f};
    for (int k0 = 0; k0 < H_; k0 += 32) {
#pragma unroll
        for (int e = 0; e < 4; e++) {
            int r = ty + e * 8;
            as[r][tx] = src[(size_t)(row0 + r) * H_ + k0 + tx];
            bs[r][tx] = src[(size_t)(k0 + r) * H_ + col0 + tx];
        }
        __syncthreads();
#pragma unroll
        for (int kk = 0; kk < 32; kk++) {
            float bv = bs[kk][tx];
#pragma unroll
            for (int e = 0; e < 4; e++) acc[e] += as[ty + e * 8][kk] * bv;
        }
        __syncthreads();
    }
#pragma unroll
    for (int e = 0; e < 4; e++)
        dst[(size_t)(row0 + ty + e * 8) * H_ + col0 + tx] = acc[e];
}

// ---------------- chunked scan (smem-staged A) ----------------
// R_=64 rows/CTA, 128 CTAs, 1 CTA/SM. Warp tile: 8 rows x 256 cols
// (lane cols {4l..4l+3, 128+4l..128+4l+3}; all gmem/LDS accesses 16B-stride).
// A is streamed per step through a 2x32KB smem double buffer (cp.async.cg,
// one tile ahead, pipelined across step boundaries) -> no L2-latency stalls.
// z double-buffered in smem (128 KB). Total smem 192 KB.
// PASS 0: zero-init scan, stores only Zend. PASS 1: from Hstart, writes out.
template <int PASS>
__global__ void __launch_bounds__(256, 1) k_scan(float* __restrict__ out) {
    extern __shared__ float sm[];
    float* zb[2] = { sm, sm + R_ * H_ };
    float* ab[2] = { sm + 2 * R_ * H_, sm + 2 * R_ * H_ + TROWS * H_ };

    const int c    = blockIdx.x & (C_ - 1);   // chunk
    const int rg   = blockIdx.x >> 5;         // row group 0..3
    const int r0   = rg * R_;
    const int tau  = threadIdx.x;
    const int w    = tau >> 5;                // warp id 0..7 -> 8 rows each
    const int l    = tau & 31;
    const int cA   = l * 4;                   // low 4 columns
    const int cB   = 128 + l * 4;             // high 4 columns

    // smem byte addresses for cp.async destinations (per-thread 16B slots)
    const uint32_t abs0 = (uint32_t)__cvta_generic_to_shared(ab[0]) + tau * 16;
    const uint32_t abs1 = (uint32_t)__cvta_generic_to_shared(ab[1]) + tau * 16;

    // init z buffer: PASS0 -> xw of first step; PASS1 -> Hstart (coalesced copy)
    {
        const float* src = (PASS == 0)
            ? (g_xw + (size_t)(c * L_) * BH + (size_t)r0 * H_)
            : (g_Hstart + (size_t)c * BH + (size_t)r0 * H_);
        const unsigned long long* s = (const unsigned long long*)src;
        unsigned long long* d = (unsigned long long*)zb[0];
#pragma unroll
        for (int k = 0; k < 32; k++) d[tau + k * 256] = s[tau + k * 256];
    }

    // A pipeline prologue: stage tiles 0 and 1
    {
        const char* s0 = (const char*)(g_At + 0 * TROWS * H_) + tau * 16;
        const char* s1 = (const char*)(g_At + 1 * TROWS * H_) + tau * 16;
#pragma unroll
        for (int i = 0; i < 8; i++) cp16(abs0 + i * 4096, s0 + i * 4096);
        cp_commit();
#pragma unroll
        for (int i = 0; i < 8; i++) cp16(abs1 + i * 4096, s1 + i * 4096);
        cp_commit();
    }
    __syncthreads();

    int p = 0;
    const int jstart = (PASS == 0) ? 2 : 1;

    for (int j = jstart; j <= L_; ++j) {
        const int t = c * L_ + j;             // global time step (1..T)
        unsigned long long acc[8][4];         // 8 rows x 4 col-u64
#pragma unroll
        for (int i = 0; i < 8; i++) {
            const float* xr = g_xw + (size_t)(t - 1) * BH
                                   + (size_t)(r0 + w * 8 + i) * H_;
            float4 xlo = __ldcs((const float4*)(xr + cA));
            float4 xhi = __ldcs((const float4*)(xr + cB));
            acc[i][0] = ((unsigned long long)__float_as_uint(xlo.y) << 32) | __float_as_uint(xlo.x);
            acc[i][1] = ((unsigned long long)__float_as_uint(xlo.w) << 32) | __float_as_uint(xlo.z);
            acc[i][2] = ((unsigned long long)__float_as_uint(xhi.y) << 32) | __float_as_uint(xhi.x);
            acc[i][3] = ((unsigned long long)__float_as_uint(xhi.w) << 32) | __float_as_uint(xhi.z);
        }
        const float* zrow = zb[p] + w * 8 * H_;

#pragma unroll 1
        for (int tk = 0; tk < 8; tk++) {      // 8 A-tiles of 32 h-rows
            cp_wait1();                        // tile tk resident
            __syncthreads();
            const float* At = ab[tk & 1];
#pragma unroll 2
            for (int hg = 0; hg < TROWS / 4; ++hg) {   // 4 h per group
                const int hbase = tk * TROWS + hg * 4;
                float4 z4[8];
#pragma unroll
                for (int i = 0; i < 8; i++)
                    z4[i] = *(const float4*)(zrow + i * H_ + hbase);
#pragma unroll
                for (int hh = 0; hh < 4; hh++) {
                    const float* arow = At + (hg * 4 + hh) * H_;
                    ulonglong2 a_lo = *(const ulonglong2*)(arow + cA);
                    ulonglong2 a_hi = *(const ulonglong2*)(arow + cB);
#pragma unroll
                    for (int i = 0; i < 8; i++) {
                        float zv = (hh == 0) ? z4[i].x
                                 : (hh == 1) ? z4[i].y
                                 : (hh == 2) ? z4[i].z : z4[i].w;
                        unsigned long long zz = pack2(zv);
                        fma2(acc[i][0], zz, a_lo.x);
                        fma2(acc[i][1], zz, a_lo.y);
                        fma2(acc[i][2], zz, a_hi.x);
                        fma2(acc[i][3], zz, a_hi.y);
                    }
                }
            }
            __syncthreads();                   // all readers done with ab[tk&1]
            // stage tile (tk+2)&7 into the freed buffer (wraps into next step)
            if (!((j == L_) && (tk >= 6))) {
                const int nt = (tk + 2) & 7;
                const uint32_t dstb = (tk & 1) ? abs1 : abs0;
                const char* s = (const char*)(g_At + nt * TROWS * H_) + tau * 16;
#pragma unroll
                for (int i = 0; i < 8; i++) cp16(dstb + i * 4096, s + i * 4096);
                cp_commit();
            }
        }

#pragma unroll
        for (int i = 0; i < 8; i++) {
            float* zw = zb[p ^ 1] + (w * 8 + i) * H_;
            *(ulonglong2*)(zw + cA) = make_ulonglong2(acc[i][0], acc[i][1]);
            *(ulonglong2*)(zw + cB) = make_ulonglong2(acc[i][2], acc[i][3]);
            if (PASS == 1) {
                float* o = out + (size_t)t * BH + (size_t)(r0 + w * 8 + i) * H_;
                __stcs((float4*)(o + cA),
                       make_float4(lof(acc[i][0]), hif(acc[i][0]),
                                   lof(acc[i][1]), hif(acc[i][1])));
                __stcs((float4*)(o + cB),
                       make_float4(lof(acc[i][2]), hif(acc[i][2]),
                                   lof(acc[i][3]), hif(acc[i][3])));
            }
        }
        __syncthreads();
        p ^= 1;
    }

    cp_wait0();   // drain any pending groups before reuse/exit

    if (PASS == 0) {
        const unsigned long long* s = (const unsigned long long*)zb[p];
        unsigned long long* d = (unsigned long long*)
            (g_Zend + (size_t)c * BH + (size_t)r0 * H_);
#pragma unroll
        for (int k = 0; k < 32; k++) d[tau + k * 256] = s[tau + k * 256];
    }
}

// ---------------- carry: Hstart[c+1] = Hstart[c] @ A^32 + Zend[c] ----------------
__global__ void __launch_bounds__(256, 1) k_carry(const float* __restrict__ h0) {
    __shared__ float hb[2][4 * H_];
    const int r0   = blockIdx.x * 4;          // 64 blocks x 4 rows
    const int tau  = threadIdx.x;
    const int rowg = tau >> 6;                // 0..3
    const int lg   = tau & 63;
    const int c0   = lg * 4;                  // 4 output cols per thread (coalesced)

    // Hstart[0] = broadcast h0
#pragma unroll
    for (int e = 0; e < 4; e++) {
        float v = h0[tau];
        hb[0][e * H_ + tau] = v;
        g_Hstart[(size_t)(r0 + e) * H_ + tau] = v;
    }
    __syncthreads();

    int p = 0;
    for (int c = 0; c < C_ - 1; c++) {
        unsigned long long acc[2];
        const unsigned long long* zs = (const unsigned long long*)
            (g_Zend + (size_t)c * BH + (size_t)(r0 + rowg) * H_ + c0);
        acc[0] = zs[0]; acc[1] = zs[1];
        const float* zr = hb[p] + rowg * H_;
#pragma unroll 4
        for (int h = 0; h < H_; h++) {
            ulonglong2 aa = *(const ulonglong2*)(g_P32 + h * H_ + c0);
            unsigned long long zz = pack2(zr[h]);
            fma2(acc[0], zz, aa.x);
            fma2(acc[1], zz, aa.y);
        }
        unsigned long long* w = (unsigned long long*)(hb[p ^ 1] + rowg * H_ + c0);
        w[0] = acc[0]; w[1] = acc[1];
        unsigned long long* g = (unsigned long long*)
            (g_Hstart + (size_t)(c + 1) * BH + (size_t)(r0 + rowg) * H_ + c0);
        g[0] = acc[0]; g[1] = acc[1];
        __syncthreads();
        p ^= 1;
    }
}

// ---------------- launch ----------------
extern "C" void kernel_launch(void* const* d_in, const int* in_sizes, int n_in,
                              void* d_out, int out_size) {
    (void)in_sizes; (void)n_in; (void)out_size;
    const float* x  = (const float*)d_in[0];
    const float* Wh = (const float*)d_in[1];
    const float* Wx = (const float*)d_in[2];
    const float* h0 = (const float*)d_in[3];
    float* out = (float*)d_out;

    const int smem = (2 * R_ * H_ + 2 * TROWS * H_) * (int)sizeof(float); // 196608
    cudaFuncSetAttribute(k_scan<0>, cudaFuncAttributeMaxDynamicSharedMemorySize, smem);
    cudaFuncSetAttribute(k_scan<1>, cudaFuncAttributeMaxDynamicSharedMemorySize, smem);

    // ncu captures MY 0-based launch index 3 -> keep k_scan<0> there.
    k_xw<<<T_, 256>>>(x, Wx);                          // 0
    k_transpose<<<256, 256>>>(Wh);                     // 1
    k_out0<<<256, 256>>>(out, h0);                     // 2
    k_scan<0><<<C_ * NRG, 256, smem>>>(out);           // 3  partials -> Zend (PROFILED)
    dim3 g8(8, 8);
    k_square<<<g8, 256>>>(0);                          // 4  A^2
    k_square<<<g8, 256>>>(1);                          // 5  A^4
    k_square<<<g8, 256>>>(2);                          // 6  A^8
    k_square<<<g8, 256>>>(3);                          // 7  A^16
    k_square<<<g8, 256>>>(4);                          // 8  A^32
    k_carry<<<B_ / 4, 256>>>(h0);                      // 9  chunk start states
    k_scan<1><<<C_ * NRG, 256, smem>>>(out);           // 10 final scan -> out
}